// round 2
// baseline (speedup 1.0000x reference)
#include <cuda_runtime.h>
#include <math.h>

// Problem dims
namespace {
constexpr int B = 256, T = 64, S = 10, H = 128, IPT = 128, Q = 128;
constexpr int ROWLEN = 2 + IPT;                       // inputs inner dim = 130
constexpr long long HSEQ_ELEMS = (long long)B * T * S * H;   // 20,971,520
constexpr long long HC_ELEMS   = (long long)B * S * H;       // 327,680
}

// ---------------- scratch (device globals; no allocation allowed) ----------------
__device__ float g_qp[B * T * S * H];   // folded+scaled q projection  (84 MB)
__device__ float g_A [B * T * 6 * H];   // precomputed gate preacts    (50 MB)
__device__ float g_pk[B * T * S * H];   // attention keys              (84 MB)
__device__ float g_pv[B * T * S * H];   // attention values            (84 MB)
__device__ float g_Wc[H * H];           // Wa @ Wattn0 * scale
__device__ float g_bc[H];               // (ba @ Wattn0 + battn0) * scale
__device__ float g_nvinv[T];            // 1/nv[t] (0 if nv==0)
__device__ float g_losspart[B];         // per-batch loss partials

__device__ __forceinline__ float sigf(float x) { return 1.f / (1.f + __expf(-x)); }

// ---------------- P2: fold q-projection weights --------------------------------
__global__ void __launch_bounds__(128) fold_kernel(
    const float* __restrict__ Wa, const float* __restrict__ ba,
    const float* __restrict__ Wattn, const float* __restrict__ battn)
{
    const int q = blockIdx.x, h = threadIdx.x;
    const float scale = 0.08838834764831845f;  // 1/sqrt(128)
    float acc = 0.f;
    for (int j = 0; j < H; ++j) acc += Wa[q * H + j] * Wattn[j * H + h];  // Wattn[0]
    g_Wc[q * H + h] = acc * scale;
    if (q == 0) {
        float bacc = battn[h];
        for (int j = 0; j < H; ++j) bacc += ba[j] * Wattn[j * H + h];
        g_bc[h] = bacc * scale;
    }
}

// ---------------- P1: precompute A[B,T,6,H] -------------------------------------
// A0..A2: px(g)+bg(g) for i,f,c~ gates; A3: o-gate with time terms;
// A4 = T1*D1; A5 = T2*D2 (fully precomputable).
__global__ void __launch_bounds__(128) pre_kernel(
    const float* __restrict__ inputs, const float* __restrict__ Wx,
    const float* __restrict__ Wts, const float* __restrict__ bg)
{
    const int b = blockIdx.x, k = threadIdx.x;
    __shared__ float xs[T][IPT];
    __shared__ float Tts[T], Dts[T];
    for (int idx = k; idx < T * IPT; idx += 128) {
        const int t = idx >> 7, i = idx & 127;
        xs[t][i] = inputs[(long long)(b * T + t) * ROWLEN + 2 + i];
    }
    if (k < T) {
        Tts[k] = inputs[(long long)(b * T + k) * ROWLEN + 0];
        Dts[k] = inputs[(long long)(b * T + k) * ROWLEN + 1];
    }
    __syncthreads();

    const float wt0 = Wts[0 * H + k], wt1 = Wts[1 * H + k];
    const float wt2 = Wts[2 * H + k], wt3 = Wts[3 * H + k];
    const float wt4 = Wts[4 * H + k], wt5 = Wts[5 * H + k];
    float bgv[8];
#pragma unroll
    for (int g = 0; g < 8; ++g) bgv[g] = bg[g * H + k];

    float* Ab = g_A + ((long long)b * T * 6) * H + k;

    for (int t0 = 0; t0 < T; t0 += 16) {
        float T1v[16], T2v[16];
#pragma unroll
        for (int g = 0; g < 8; ++g) {
            float acc[16];
#pragma unroll
            for (int tt = 0; tt < 16; ++tt) acc[tt] = 0.f;
            const float* Wg = Wx + (long long)g * IPT * H + k;
            for (int i = 0; i < IPT; ++i) {
                const float w = Wg[(long long)i * H];
#pragma unroll
                for (int tt = 0; tt < 16; ++tt) acc[tt] += xs[t0 + tt][i] * w;
            }
#pragma unroll
            for (int tt = 0; tt < 16; ++tt) {
                const int t = t0 + tt;
                const float v = acc[tt];
                float* At = Ab + (long long)t * 6 * H;
                if (g == 0)      At[0]     = v + bgv[0];
                else if (g == 1) At[H]     = v + bgv[1];
                else if (g == 2) At[2 * H] = v + bgv[2];
                else if (g == 3) At[3 * H] = v + Tts[t] * wt4 + Dts[t] * wt5 + bgv[3];
                else if (g == 4) T1v[tt] = sigf(v + sigf(Tts[t] * wt0) + bgv[4]);
                else if (g == 5) T2v[tt] = sigf(v + sigf(Tts[t] * wt1) + bgv[5]);
                else if (g == 6) At[4 * H] = T1v[tt] * sigf(v + sigf(Dts[t] * wt2) + bgv[6]);
                else             At[5 * H] = T2v[tt] * sigf(v + sigf(Dts[t] * wt3) + bgv[7]);
            }
        }
    }
}

// ---------------- P3: qp = x_q @ Wc + bc (scale folded in) ----------------------
__global__ void __launch_bounds__(128) qp_kernel(const float* __restrict__ x_q)
{
    const int bt = blockIdx.x, k = threadIdx.x;
    __shared__ float xq[S][Q];
    const float* xp = x_q + (long long)bt * S * Q;
    for (int idx = k; idx < S * Q; idx += 128) xq[idx >> 7][idx & 127] = xp[idx];
    __syncthreads();
    float acc[S];
    const float bcv = g_bc[k];
#pragma unroll
    for (int s = 0; s < S; ++s) acc[s] = bcv;
    for (int i = 0; i < Q; ++i) {
        const float w = g_Wc[i * H + k];
#pragma unroll
        for (int s = 0; s < S; ++s) acc[s] += xq[s][i] * w;
    }
    float* o = g_qp + (long long)bt * S * H + k;
#pragma unroll
    for (int s = 0; s < S; ++s) o[s * H] = acc[s];
}

// ---------------- P4: nv[t] ------------------------------------------------------
__global__ void nv_kernel(const int* __restrict__ keys_length)
{
    const int t = threadIdx.x;
    if (t < T) {
        int cnt = 0;
        for (int b = 0; b < B; ++b) cnt += (t < keys_length[b]) ? 1 : 0;
        g_nvinv[t] = (cnt > 0) ? 1.f / (float)cnt : 0.f;
    }
}

// ---------------- recurrent kernel: one CTA per batch element -------------------
__global__ void __launch_bounds__(128) rec_kernel(
    const float* __restrict__ Wh, const float* __restrict__ Wattn,
    const float* __restrict__ battn, const float* __restrict__ austgn_y,
    const int* __restrict__ keys_length, float* __restrict__ out)
{
    const int b = blockIdx.x;
    const int k = threadIdx.x;        // output column 0..127
    const int lane = k & 31, warp = k >> 5;

    __shared__ float hsm[S][H];       // current hidden state
    __shared__ float buf[S][H];       // ctx staging
    __shared__ float qps[S][H];       // qp for current step
    __shared__ float ssm[S][T];       // scores / softmax probs
    __shared__ float red[4];

    const int kl = keys_length[b];
    float c[S], at[S];
#pragma unroll
    for (int s = 0; s < S; ++s) { hsm[s][k] = 0.f; c[s] = 0.f; }
    __syncthreads();

    const float* W1 = Wattn + 1 * H * H;
    const float* W2 = Wattn + 2 * H * H;
    const float* W3 = Wattn + 3 * H * H;
    const float b1 = battn[1 * H + k], b2 = battn[2 * H + k], b3 = battn[3 * H + k];
    float lossacc = 0.f;

    int t = 0;
    for (; t < kl; ++t) {
        // ================= attention =================
        if (t == 0) {
#pragma unroll
            for (int s = 0; s < S; ++s) at[s] = 1.f;
        } else {
            const float* qpp = g_qp + ((long long)(b * T + t) * S) * H;
#pragma unroll
            for (int s = 0; s < S; ++s) qps[s][k] = qpp[s * H + k];
            __syncthreads();

            // scores: S*t dot products of length H, one per warp-iteration
            const int nd = S * t;
            for (int idx = warp; idx < nd; idx += 4) {
                const int s  = idx % S;
                const int tp = idx / S;
                const float* pkr = g_pk + ((long long)((b * T + tp) * S + s)) * H;
                float acc = 0.f;
#pragma unroll
                for (int j = 0; j < 4; ++j) acc += qps[s][lane + 32 * j] * pkr[lane + 32 * j];
#pragma unroll
                for (int o = 16; o > 0; o >>= 1) acc += __shfl_xor_sync(0xffffffffu, acc, o);
                if (lane == 0) ssm[s][tp] = acc;
            }
            __syncthreads();

            // softmax per s over t' in [0, t)
            for (int s = warp; s < S; s += 4) {
                float mx = -1e30f;
                for (int tp = lane; tp < t; tp += 32) mx = fmaxf(mx, ssm[s][tp]);
#pragma unroll
                for (int o = 16; o > 0; o >>= 1) mx = fmaxf(mx, __shfl_xor_sync(0xffffffffu, mx, o));
                float sum = 0.f;
                for (int tp = lane; tp < t; tp += 32) {
                    const float e = __expf(ssm[s][tp] - mx);
                    ssm[s][tp] = e; sum += e;
                }
#pragma unroll
                for (int o = 16; o > 0; o >>= 1) sum += __shfl_xor_sync(0xffffffffu, sum, o);
                const float inv = 1.f / sum;
                for (int tp = lane; tp < t; tp += 32) ssm[s][tp] *= inv;
            }
            __syncthreads();

            // ctx[s][k] = sum_tp p[s][tp] * pv[b,tp,s,k]
            float ctx[S];
#pragma unroll
            for (int s = 0; s < S; ++s) ctx[s] = 0.f;
            const float* pvb = g_pv + ((long long)b * T * S) * H + k;
#pragma unroll 2
            for (int tp = 0; tp < t; ++tp) {
                const float* pvr = pvb + (long long)tp * S * H;
#pragma unroll
                for (int s = 0; s < S; ++s) ctx[s] += ssm[s][tp] * pvr[s * H];
            }
#pragma unroll
            for (int s = 0; s < S; ++s) buf[s][k] = ctx[s];
            __syncthreads();

            // at = ctx @ Wattn3 + battn3
#pragma unroll
            for (int s = 0; s < S; ++s) at[s] = b3;
#pragma unroll 2
            for (int h = 0; h < H; ++h) {
                const float w = W3[h * H + k];
#pragma unroll
                for (int s = 0; s < S; ++s) at[s] += buf[s][h] * w;
            }
        }

        // ================= gate GEMM: ph[g] = h @ Wh[g] =================
        float g0[S], g1[S], g2[S], g3[S];
#pragma unroll
        for (int s = 0; s < S; ++s) { g0[s] = 0.f; g1[s] = 0.f; g2[s] = 0.f; g3[s] = 0.f; }
        const float* Whk = Wh + k;
#pragma unroll 2
        for (int h = 0; h < H; ++h) {
            const float w0 = Whk[h * H];
            const float w1 = Whk[H * H + h * H];
            const float w2 = Whk[2 * H * H + h * H];
            const float w3 = Whk[3 * H * H + h * H];
#pragma unroll
            for (int s = 0; s < S; ++s) {
                const float hv = hsm[s][h];
                g0[s] += hv * w0; g1[s] += hv * w1; g2[s] += hv * w2; g3[s] += hv * w3;
            }
        }

        // ================= elementwise LSTM cell =================
        const float* Ab = g_A + ((long long)((b * T + t) * 6)) * H + k;
        const float a0 = Ab[0], a1 = Ab[H], a2 = Ab[2 * H], a3 = Ab[3 * H];
        const float td1 = Ab[4 * H], td2 = Ab[5 * H];
        const float y = austgn_y[b * T + t];
        float hw[S];
        float bsum = 0.f;
#pragma unroll
        for (int s = 0; s < S; ++s) {
            const float it = sigf(a0 + g0[s]);
            const float ft = sigf(a1 + g1[s]);
            const float ct = tanhf(a2 + g2[s]);
            const float ot = sigf(a3 + g3[s]);
            const float itp = it * at[s], ftp = ft * at[s];
            const float fc = ftp * c[s];
            const float ic = itp * ct;
            const float chat = fc + ic * td1;
            c[s] = fc + ic * td2;                 // c_new (mask is true for t < kl)
            const float hn = ot * tanhf(chat);
            hw[s] = hn;
            const float p = fminf(fmaxf(hn, 1e-7f), 1.f - 1e-7f);
            bsum += -(y * __logf(p) + (1.f - y) * log1pf(-p));
        }
        lossacc += bsum * g_nvinv[t];

        __syncthreads();                           // done reading old hsm
#pragma unroll
        for (int s = 0; s < S; ++s) hsm[s][k] = hw[s];
        __syncthreads();

        // hidden_seq_attn output
        float* outp = out + ((long long)((b * T + t) * S)) * H + k;
#pragma unroll
        for (int s = 0; s < S; ++s) outp[s * H] = hw[s];

        // pk/pv rows for this step: h_w @ Wattn1/2 + battn1/2
        float pkv[S], pvv[S];
#pragma unroll
        for (int s = 0; s < S; ++s) { pkv[s] = b1; pvv[s] = b2; }
#pragma unroll 2
        for (int h = 0; h < H; ++h) {
            const float w1 = W1[h * H + k];
            const float w2 = W2[h * H + k];
#pragma unroll
            for (int s = 0; s < S; ++s) {
                const float hv = hsm[s][h];
                pkv[s] += hv * w1; pvv[s] += hv * w2;
            }
        }
        float* pkp = g_pk + ((long long)((b * T + t) * S)) * H + k;
        float* pvp = g_pv + ((long long)((b * T + t) * S)) * H + k;
#pragma unroll
        for (int s = 0; s < S; ++s) { pkp[s * H] = pkv[s]; pvp[s * H] = pvv[s]; }
        __syncthreads();   // make pk/pv visible before next step's attention
    }

    // masked (inactive) steps: hidden output is exactly zero
    for (; t < T; ++t) {
        float* outp = out + ((long long)((b * T + t) * S)) * H + k;
#pragma unroll
        for (int s = 0; s < S; ++s) outp[s * H] = 0.f;
    }

    // final h, c
    float* oh = out + HSEQ_ELEMS + ((long long)b * S) * H + k;
#pragma unroll
    for (int s = 0; s < S; ++s) oh[s * H] = hsm[s][k];
    float* oc = oh + HC_ELEMS;
#pragma unroll
    for (int s = 0; s < S; ++s) oc[s * H] = c[s];

    // per-block loss partial (deterministic tree reduce)
    float v = lossacc;
#pragma unroll
    for (int o = 16; o > 0; o >>= 1) v += __shfl_xor_sync(0xffffffffu, v, o);
    if (lane == 0) red[warp] = v;
    __syncthreads();
    if (k == 0) g_losspart[b] = (red[0] + red[1] + red[2] + red[3]) * (1.f / (float)(S * H));
}

// ---------------- final deterministic loss reduction ----------------------------
__global__ void loss_kernel(float* __restrict__ out)
{
    __shared__ float sm[B];
    sm[threadIdx.x] = g_losspart[threadIdx.x];
    __syncthreads();
    for (int off = B / 2; off > 0; off >>= 1) {
        if (threadIdx.x < off) sm[threadIdx.x] += sm[threadIdx.x + off];
        __syncthreads();
    }
    if (threadIdx.x == 0) out[HSEQ_ELEMS + 2 * HC_ELEMS] = sm[0];
}

// ---------------- launch ---------------------------------------------------------
extern "C" void kernel_launch(void* const* d_in, const int* in_sizes, int n_in,
                              void* d_out, int out_size)
{
    (void)in_sizes; (void)n_in; (void)out_size;
    const float* inputs      = (const float*)d_in[0];
    const float* x_q         = (const float*)d_in[1];
    const float* austgn_y    = (const float*)d_in[2];
    const int*   keys_length = (const int*)  d_in[3];
    const float* Wx          = (const float*)d_in[4];
    const float* Wh          = (const float*)d_in[5];
    const float* Wts         = (const float*)d_in[6];
    const float* bg          = (const float*)d_in[7];
    const float* Wa          = (const float*)d_in[8];
    const float* ba          = (const float*)d_in[9];
    const float* Wattn       = (const float*)d_in[10];
    const float* battn       = (const float*)d_in[11];
    float* out = (float*)d_out;

    fold_kernel<<<H, H>>>(Wa, ba, Wattn, battn);
    pre_kernel<<<B, 128>>>(inputs, Wx, Wts, bg);
    qp_kernel<<<B * T, 128>>>(x_q);
    nv_kernel<<<1, 64>>>(keys_length);
    rec_kernel<<<B, 128>>>(Wh, Wattn, battn, austgn_y, keys_length, out);
    loss_kernel<<<1, B>>>(out);
}

// round 3
// speedup vs baseline: 1.3975x; 1.3975x over previous
#include <cuda_runtime.h>
#include <math.h>

namespace {
constexpr int B = 256, T = 64, S = 10, H = 128, IPT = 128, Q = 128;
constexpr int ROWLEN = 2 + IPT;
constexpr long long HSEQ_ELEMS = (long long)B * T * S * H;
constexpr long long HC_ELEMS   = (long long)B * S * H;
}

// ---------------- scratch ----------------
__device__ float g_qp[B * T * S * H];
__device__ float g_A [B * T * 6 * H];
__device__ float g_pk[B * T * S * H];
__device__ float g_pv[B * T * S * H];
__device__ float g_Wc[H * H];
__device__ float g_bc[H];
__device__ float g_nvinv[T];
__device__ float g_losspart[B];
__device__ int   g_perm[B];

// ---------------- f32x2 helpers ----------------
using u64 = unsigned long long;
__device__ __forceinline__ u64 pk2(float lo, float hi) {
    u64 r; asm("mov.b64 %0,{%1,%2};" : "=l"(r) : "f"(lo), "f"(hi)); return r;
}
__device__ __forceinline__ u64 dup2(float x) { return pk2(x, x); }
__device__ __forceinline__ void un2(u64 v, float& a, float& b) {
    asm("mov.b64 {%0,%1},%2;" : "=f"(a), "=f"(b) : "l"(v));
}
__device__ __forceinline__ void fma2(u64& d, u64 a, u64 b) {
    asm("fma.rn.f32x2 %0,%1,%2,%0;" : "+l"(d) : "l"(a), "l"(b));
}

__device__ __forceinline__ float sigf(float x) {
    return __fdividef(1.f, 1.f + __expf(-x));
}
__device__ __forceinline__ float tanhfast(float x) {
    return __fdividef(2.f, 1.f + __expf(-2.f * x)) - 1.f;
}

// ---------------- fold q-projection weights ----------------
__global__ void __launch_bounds__(128) fold_kernel(
    const float* __restrict__ Wa, const float* __restrict__ ba,
    const float* __restrict__ Wattn, const float* __restrict__ battn)
{
    const int q = blockIdx.x, h = threadIdx.x;
    const float scale = 0.08838834764831845f;
    float acc = 0.f;
    for (int j = 0; j < H; ++j) acc += Wa[q * H + j] * Wattn[j * H + h];
    g_Wc[q * H + h] = acc * scale;
    if (q == 0) {
        float bacc = battn[h];
        for (int j = 0; j < H; ++j) bacc += ba[j] * Wattn[j * H + h];
        g_bc[h] = bacc * scale;
    }
}

// ---------------- precompute A[B,T,6,H] (f32x2) ----------------
__global__ void __launch_bounds__(128) pre_kernel(
    const float* __restrict__ inputs, const float* __restrict__ Wx,
    const float* __restrict__ Wts, const float* __restrict__ bg)
{
    const int b = blockIdx.x, k = threadIdx.x;
    __shared__ float xsT[IPT][66];     // transposed, padded (pairs 8B-aligned)
    __shared__ float Tts[T], Dts[T];
    for (int idx = k; idx < T * IPT; idx += 128) {
        const int t = idx >> 7, i = idx & 127;
        xsT[i][t] = inputs[(long long)(b * T + t) * ROWLEN + 2 + i];
    }
    if (k < T) {
        Tts[k] = inputs[(long long)(b * T + k) * ROWLEN + 0];
        Dts[k] = inputs[(long long)(b * T + k) * ROWLEN + 1];
    }
    __syncthreads();

    const float wt0 = Wts[0 * H + k], wt1 = Wts[1 * H + k];
    const float wt2 = Wts[2 * H + k], wt3 = Wts[3 * H + k];
    const float wt4 = Wts[4 * H + k], wt5 = Wts[5 * H + k];
    float bgv[8];
#pragma unroll
    for (int g = 0; g < 8; ++g) bgv[g] = bg[g * H + k];

    float* Ab = g_A + ((long long)b * T * 6) * H + k;

    for (int t0 = 0; t0 < T; t0 += 16) {
        float T1v[16], T2v[16];
#pragma unroll
        for (int g = 0; g < 8; ++g) {
            u64 acc[8];
#pragma unroll
            for (int j = 0; j < 8; ++j) acc[j] = 0ull;
            const float* Wg = Wx + (long long)g * IPT * H + k;
#pragma unroll 4
            for (int i = 0; i < IPT; ++i) {
                const u64 wd = dup2(Wg[(long long)i * H]);
#pragma unroll
                for (int j = 0; j < 8; ++j)
                    fma2(acc[j], *(const u64*)&xsT[i][t0 + 2 * j], wd);
            }
#pragma unroll
            for (int j = 0; j < 8; ++j) {
                float v0, v1; un2(acc[j], v0, v1);
#pragma unroll
                for (int half = 0; half < 2; ++half) {
                    const int tt = 2 * j + half;
                    const int t = t0 + tt;
                    const float v = half ? v1 : v0;
                    float* At = Ab + (long long)t * 6 * H;
                    if (g == 0)      At[0]     = v + bgv[0];
                    else if (g == 1) At[H]     = v + bgv[1];
                    else if (g == 2) At[2 * H] = v + bgv[2];
                    else if (g == 3) At[3 * H] = v + Tts[t] * wt4 + Dts[t] * wt5 + bgv[3];
                    else if (g == 4) T1v[tt] = sigf(v + sigf(Tts[t] * wt0) + bgv[4]);
                    else if (g == 5) T2v[tt] = sigf(v + sigf(Tts[t] * wt1) + bgv[5]);
                    else if (g == 6) At[4 * H] = T1v[tt] * sigf(v + sigf(Dts[t] * wt2) + bgv[6]);
                    else             At[5 * H] = T2v[tt] * sigf(v + sigf(Dts[t] * wt3) + bgv[7]);
                }
            }
        }
    }
}

// ---------------- qp = x_q @ Wc + bc (f32x2) ----------------
__global__ void __launch_bounds__(128) qp_kernel(const float* __restrict__ x_q)
{
    const int bt = blockIdx.x, k = threadIdx.x;
    __shared__ float xqT[Q][12];       // transposed x_q, pairs 8B-aligned
    const float* xp = x_q + (long long)bt * S * Q;
    for (int idx = k; idx < S * Q; idx += 128) {
        const int s = idx >> 7, q = idx & 127;
        xqT[q][s] = xp[idx];
    }
    __syncthreads();
    const float bcv = g_bc[k];
    u64 acc[5];
#pragma unroll
    for (int p = 0; p < 5; ++p) acc[p] = dup2(bcv);
#pragma unroll 4
    for (int i = 0; i < Q; ++i) {
        const u64 wd = dup2(g_Wc[i * H + k]);
#pragma unroll
        for (int p = 0; p < 5; ++p)
            fma2(acc[p], *(const u64*)&xqT[i][2 * p], wd);
    }
    float* o = g_qp + (long long)bt * S * H + k;
#pragma unroll
    for (int p = 0; p < 5; ++p) {
        float v0, v1; un2(acc[p], v0, v1);
        o[(2 * p) * H] = v0; o[(2 * p + 1) * H] = v1;
    }
}

// ---------------- perm (kl descending, stable) + nvinv ----------------
__global__ void __launch_bounds__(256) perm_kernel(const int* __restrict__ keys_length)
{
    __shared__ int kls[B];
    const int b = threadIdx.x;
    kls[b] = keys_length[b];
    __syncthreads();
    const int kb = kls[b];
    int rank = 0;
    for (int j = 0; j < B; ++j) {
        const int kj = kls[j];
        rank += (kj > kb) || (kj == kb && j < b);
    }
    g_perm[rank] = b;
    if (b < T) {
        int cnt = 0;
        for (int j = 0; j < B; ++j) cnt += (b < kls[j]) ? 1 : 0;
        g_nvinv[b] = cnt ? 1.f / (float)cnt : 0.f;
    }
}

// ---------------- recurrent kernel ----------------
__global__ void __launch_bounds__(128) rec_kernel(
    const float* __restrict__ Wh, const float* __restrict__ Wattn,
    const float* __restrict__ battn, const float* __restrict__ austgn_y,
    const int* __restrict__ keys_length, float* __restrict__ out)
{
    const int b = g_perm[blockIdx.x];
    const int k = threadIdx.x;
    const int lane = k & 31, warp = k >> 5;

    __shared__ float hT[H][12];       // hidden state, transposed [h][s]
    __shared__ float bufT[H][12];     // ctx, transposed [h][s]
    __shared__ float qps[S][H];
    __shared__ float ssm[S][T];
    __shared__ float red[4];

    const int kl = keys_length[b];
    float c[S], at[S];
#pragma unroll
    for (int s = 0; s < S; ++s) c[s] = 0.f;
#pragma unroll
    for (int p = 0; p < 5; ++p) *(u64*)&hT[k][2 * p] = 0ull;
    __syncthreads();

    const float* W1 = Wattn + 1 * H * H;
    const float* W2 = Wattn + 2 * H * H;
    const float* W3 = Wattn + 3 * H * H;
    const float b1 = battn[1 * H + k], b2 = battn[2 * H + k], b3 = battn[3 * H + k];
    float lossacc = 0.f;

    int t = 0;
    for (; t < kl; ++t) {
        // ========== attention ==========
        if (t == 0) {
#pragma unroll
            for (int s = 0; s < S; ++s) at[s] = 1.f;
        } else {
            const float* qpp = g_qp + ((long long)(b * T + t) * S) * H;
#pragma unroll
            for (int s = 0; s < S; ++s) qps[s][k] = qpp[s * H + k];
            __syncthreads();

            // scores (float2 loads)
            const int nd = S * t;
            for (int idx = warp; idx < nd; idx += 4) {
                const int s  = idx % S;
                const int tp = idx / S;
                const float* pkr = g_pk + ((long long)((b * T + tp) * S + s)) * H;
                float acc = 0.f;
#pragma unroll
                for (int j = 0; j < 2; ++j) {
                    const float2 q2 = *(const float2*)&qps[s][2 * lane + 64 * j];
                    const float2 k2 = *(const float2*)&pkr[2 * lane + 64 * j];
                    acc += q2.x * k2.x + q2.y * k2.y;
                }
#pragma unroll
                for (int o = 16; o > 0; o >>= 1) acc += __shfl_xor_sync(0xffffffffu, acc, o);
                if (lane == 0) ssm[s][tp] = acc;
            }
            __syncthreads();

            // softmax per s
            for (int s = warp; s < S; s += 4) {
                float mx = -1e30f;
                for (int tp = lane; tp < t; tp += 32) mx = fmaxf(mx, ssm[s][tp]);
#pragma unroll
                for (int o = 16; o > 0; o >>= 1) mx = fmaxf(mx, __shfl_xor_sync(0xffffffffu, mx, o));
                float sum = 0.f;
                for (int tp = lane; tp < t; tp += 32) {
                    const float e = __expf(ssm[s][tp] - mx);
                    ssm[s][tp] = e; sum += e;
                }
#pragma unroll
                for (int o = 16; o > 0; o >>= 1) sum += __shfl_xor_sync(0xffffffffu, sum, o);
                const float inv = __fdividef(1.f, sum);
                for (int tp = lane; tp < t; tp += 32) ssm[s][tp] *= inv;
            }
            __syncthreads();

            // ctx[s] = sum_tp p[s][tp] * pv[b,tp,s,k]  -> bufT[k][s]
            float ctx[S];
#pragma unroll
            for (int s = 0; s < S; ++s) ctx[s] = 0.f;
            const float* pvb = g_pv + ((long long)b * T * S) * H + k;
#pragma unroll 2
            for (int tp = 0; tp < t; ++tp) {
                const float* pvr = pvb + (long long)tp * S * H;
#pragma unroll
                for (int s = 0; s < S; ++s) ctx[s] += ssm[s][tp] * pvr[s * H];
            }
#pragma unroll
            for (int s = 0; s < S; ++s) bufT[k][s] = ctx[s];
            __syncthreads();

            // at = ctx @ Wattn3 + battn3   (f32x2, s-pairs)
            u64 acc3[5];
#pragma unroll
            for (int p = 0; p < 5; ++p) acc3[p] = dup2(b3);
#pragma unroll 4
            for (int h = 0; h < H; ++h) {
                const u64 wd = dup2(W3[h * H + k]);
#pragma unroll
                for (int p = 0; p < 5; ++p)
                    fma2(acc3[p], *(const u64*)&bufT[h][2 * p], wd);
            }
#pragma unroll
            for (int p = 0; p < 5; ++p) un2(acc3[p], at[2 * p], at[2 * p + 1]);
        }

        // ========== gate GEMM (f32x2, s-pairs) ==========
        u64 a0p[5], a1p[5], a2p[5], a3p[5];
#pragma unroll
        for (int p = 0; p < 5; ++p) { a0p[p] = 0ull; a1p[p] = 0ull; a2p[p] = 0ull; a3p[p] = 0ull; }
        const float* Whk = Wh + k;
#pragma unroll 4
        for (int h = 0; h < H; ++h) {
            const u64 w0 = dup2(Whk[h * H]);
            const u64 w1 = dup2(Whk[H * H + h * H]);
            const u64 w2 = dup2(Whk[2 * H * H + h * H]);
            const u64 w3 = dup2(Whk[3 * H * H + h * H]);
#pragma unroll
            for (int p = 0; p < 5; ++p) {
                const u64 hp = *(const u64*)&hT[h][2 * p];
                fma2(a0p[p], hp, w0); fma2(a1p[p], hp, w1);
                fma2(a2p[p], hp, w2); fma2(a3p[p], hp, w3);
            }
        }
        float g0[S], g1[S], g2[S], g3[S];
#pragma unroll
        for (int p = 0; p < 5; ++p) {
            un2(a0p[p], g0[2 * p], g0[2 * p + 1]);
            un2(a1p[p], g1[2 * p], g1[2 * p + 1]);
            un2(a2p[p], g2[2 * p], g2[2 * p + 1]);
            un2(a3p[p], g3[2 * p], g3[2 * p + 1]);
        }

        // ========== elementwise LSTM cell ==========
        const float* Ab = g_A + ((long long)((b * T + t) * 6)) * H + k;
        const float a0 = Ab[0], a1 = Ab[H], a2 = Ab[2 * H], a3 = Ab[3 * H];
        const float td1 = Ab[4 * H], td2 = Ab[5 * H];
        const float y = austgn_y[b * T + t];
        float hw[S];
        float bsum = 0.f;
#pragma unroll
        for (int s = 0; s < S; ++s) {
            const float it = sigf(a0 + g0[s]);
            const float ft = sigf(a1 + g1[s]);
            const float ct = tanhfast(a2 + g2[s]);
            const float ot = sigf(a3 + g3[s]);
            const float itp = it * at[s], ftp = ft * at[s];
            const float fc = ftp * c[s];
            const float ic = itp * ct;
            const float chat = fc + ic * td1;
            c[s] = fc + ic * td2;
            const float hn = ot * tanhfast(chat);
            hw[s] = hn;
            const float p = fminf(fmaxf(hn, 1e-7f), 1.f - 1e-7f);
            bsum += -(y * __logf(p) + (1.f - y) * __logf(1.f - p));
        }
        lossacc += bsum * g_nvinv[t];

        __syncthreads();                 // all readers of old hT done
#pragma unroll
        for (int s = 0; s < S; ++s) hT[k][s] = hw[s];
        __syncthreads();

        // hidden_seq_attn output
        float* outp = out + ((long long)((b * T + t) * S)) * H + k;
#pragma unroll
        for (int s = 0; s < S; ++s) outp[s * H] = hw[s];

        // pk/pv GEMM (f32x2, s-pairs)
        u64 apk[5], apv[5];
#pragma unroll
        for (int p = 0; p < 5; ++p) { apk[p] = dup2(b1); apv[p] = dup2(b2); }
#pragma unroll 4
        for (int h = 0; h < H; ++h) {
            const u64 w1 = dup2(W1[h * H + k]);
            const u64 w2 = dup2(W2[h * H + k]);
#pragma unroll
            for (int p = 0; p < 5; ++p) {
                const u64 hp = *(const u64*)&hT[h][2 * p];
                fma2(apk[p], hp, w1); fma2(apv[p], hp, w2);
            }
        }
        float* pkp = g_pk + ((long long)((b * T + t) * S)) * H + k;
        float* pvp = g_pv + ((long long)((b * T + t) * S)) * H + k;
#pragma unroll
        for (int p = 0; p < 5; ++p) {
            float v0, v1; un2(apk[p], v0, v1);
            pkp[(2 * p) * H] = v0; pkp[(2 * p + 1) * H] = v1;
            un2(apv[p], v0, v1);
            pvp[(2 * p) * H] = v0; pvp[(2 * p + 1) * H] = v1;
        }
        __syncthreads();                 // pk/pv visible before next step
    }

    // masked steps: zeros
    for (; t < T; ++t) {
        float* outp = out + ((long long)((b * T + t) * S)) * H + k;
#pragma unroll
        for (int s = 0; s < S; ++s) outp[s * H] = 0.f;
    }

    // final h, c
    float* oh = out + HSEQ_ELEMS + ((long long)b * S) * H + k;
#pragma unroll
    for (int s = 0; s < S; ++s) oh[s * H] = hT[k][s];
    float* oc = oh + HC_ELEMS;
#pragma unroll
    for (int s = 0; s < S; ++s) oc[s * H] = c[s];

    // per-block loss partial
    float v = lossacc;
#pragma unroll
    for (int o = 16; o > 0; o >>= 1) v += __shfl_xor_sync(0xffffffffu, v, o);
    if (lane == 0) red[warp] = v;
    __syncthreads();
    if (k == 0) g_losspart[b] = (red[0] + red[1] + red[2] + red[3]) * (1.f / (float)(S * H));
}

// ---------------- final loss reduction ----------------
__global__ void loss_kernel(float* __restrict__ out)
{
    __shared__ float sm[B];
    sm[threadIdx.x] = g_losspart[threadIdx.x];
    __syncthreads();
    for (int off = B / 2; off > 0; off >>= 1) {
        if (threadIdx.x < off) sm[threadIdx.x] += sm[threadIdx.x + off];
        __syncthreads();
    }
    if (threadIdx.x == 0) out[HSEQ_ELEMS + 2 * HC_ELEMS] = sm[0];
}

// ---------------- launch ----------------
extern "C" void kernel_launch(void* const* d_in, const int* in_sizes, int n_in,
                              void* d_out, int out_size)
{
    (void)in_sizes; (void)n_in; (void)out_size;
    const float* inputs      = (const float*)d_in[0];
    const float* x_q         = (const float*)d_in[1];
    const float* austgn_y    = (const float*)d_in[2];
    const int*   keys_length = (const int*)  d_in[3];
    const float* Wx          = (const float*)d_in[4];
    const float* Wh          = (const float*)d_in[5];
    const float* Wts         = (const float*)d_in[6];
    const float* bg          = (const float*)d_in[7];
    const float* Wa          = (const float*)d_in[8];
    const float* ba          = (const float*)d_in[9];
    const float* Wattn       = (const float*)d_in[10];
    const float* battn       = (const float*)d_in[11];
    float* out = (float*)d_out;

    fold_kernel<<<H, H>>>(Wa, ba, Wattn, battn);
    pre_kernel<<<B, 128>>>(inputs, Wx, Wts, bg);
    qp_kernel<<<B * T, 128>>>(x_q);
    perm_kernel<<<1, B>>>(keys_length);
    rec_kernel<<<B, 128>>>(Wh, Wattn, battn, austgn_y, keys_length, out);
    loss_kernel<<<1, B>>>(out);
}

// round 4
// speedup vs baseline: 2.7118x; 1.9405x over previous
#include <cuda_runtime.h>
#include <math.h>

namespace {
constexpr int B = 256, T = 64, S = 10, H = 128, IPT = 128, Q = 128;
constexpr int ROWLEN = 2 + IPT;
constexpr int HH = H * H;
constexpr long long HSEQ_ELEMS = (long long)B * T * S * H;
constexpr long long HC_ELEMS   = (long long)B * S * H;
// dynamic smem layout (float offsets)
constexpr int SM_W1  = 0;
constexpr int SM_W2  = SM_W1 + HH;
constexpr int SM_W3  = SM_W2 + HH;
constexpr int SM_HT  = SM_W3 + HH;          // [128][12]
constexpr int SM_BUF = SM_HT + H * 12;      // [128][12]
constexpr int SM_QPS = SM_BUF + H * 12;     // [10][128]
constexpr int SM_SSM = SM_QPS + S * H;      // [10][64]
constexpr int SM_ST2 = SM_SSM + S * T;      // [10][128]
constexpr int SM_ST3 = SM_ST2 + S * H;      // [10][128]
constexpr int SM_ATS = SM_ST3 + S * H;      // [6][128]
constexpr int SM_RED = SM_ATS + 6 * H;      // [8]
constexpr int SM_TOTAL = SM_RED + 8;        // 57480 floats = 229920 B
}

// ---------------- scratch ----------------
__device__ float g_qp[B * T * S * H];
__device__ float g_A [B * T * 6 * H];
__device__ float g_pk[B * T * S * H];
__device__ float g_pv[B * T * S * H];
__device__ float g_Wc[H * H];
__device__ float g_bc[H];
__device__ float g_nvinv[T];
__device__ float g_losspart[B];
__device__ int   g_perm[B];

// ---------------- f32x2 helpers ----------------
using u64 = unsigned long long;
__device__ __forceinline__ u64 pk2(float lo, float hi) {
    u64 r; asm("mov.b64 %0,{%1,%2};" : "=l"(r) : "f"(lo), "f"(hi)); return r;
}
__device__ __forceinline__ u64 dup2(float x) { return pk2(x, x); }
__device__ __forceinline__ void un2(u64 v, float& a, float& b) {
    asm("mov.b64 {%0,%1},%2;" : "=f"(a), "=f"(b) : "l"(v));
}
__device__ __forceinline__ void fma2(u64& d, u64 a, u64 b) {
    asm("fma.rn.f32x2 %0,%1,%2,%0;" : "+l"(d) : "l"(a), "l"(b));
}

__device__ __forceinline__ float sigf(float x) {
    return __fdividef(1.f, 1.f + __expf(-x));
}
__device__ __forceinline__ float tanhfast(float x) {
    return __fdividef(2.f, 1.f + __expf(-2.f * x)) - 1.f;
}

// ---------------- fold q-projection weights ----------------
__global__ void __launch_bounds__(128) fold_kernel(
    const float* __restrict__ Wa, const float* __restrict__ ba,
    const float* __restrict__ Wattn, const float* __restrict__ battn)
{
    const int q = blockIdx.x, h = threadIdx.x;
    const float scale = 0.08838834764831845f;
    float acc = 0.f;
    for (int j = 0; j < H; ++j) acc += Wa[q * H + j] * Wattn[j * H + h];
    g_Wc[q * H + h] = acc * scale;
    if (q == 0) {
        float bacc = battn[h];
        for (int j = 0; j < H; ++j) bacc += ba[j] * Wattn[j * H + h];
        g_bc[h] = bacc * scale;
    }
}

// ---------------- precompute A[B,T,6,H] ----------------
__global__ void __launch_bounds__(128) pre_kernel(
    const float* __restrict__ inputs, const float* __restrict__ Wx,
    const float* __restrict__ Wts, const float* __restrict__ bg)
{
    const int b = blockIdx.x, k = threadIdx.x;
    __shared__ float xsT[IPT][66];
    __shared__ float Tts[T], Dts[T];
    for (int idx = k; idx < T * IPT; idx += 128) {
        const int t = idx >> 7, i = idx & 127;
        xsT[i][t] = inputs[(long long)(b * T + t) * ROWLEN + 2 + i];
    }
    if (k < T) {
        Tts[k] = inputs[(long long)(b * T + k) * ROWLEN + 0];
        Dts[k] = inputs[(long long)(b * T + k) * ROWLEN + 1];
    }
    __syncthreads();

    const float wt0 = Wts[0 * H + k], wt1 = Wts[1 * H + k];
    const float wt2 = Wts[2 * H + k], wt3 = Wts[3 * H + k];
    const float wt4 = Wts[4 * H + k], wt5 = Wts[5 * H + k];
    float bgv[8];
#pragma unroll
    for (int g = 0; g < 8; ++g) bgv[g] = bg[g * H + k];

    float* Ab = g_A + ((long long)b * T * 6) * H + k;

    for (int t0 = 0; t0 < T; t0 += 16) {
        float T1v[16], T2v[16];
#pragma unroll
        for (int g = 0; g < 8; ++g) {
            u64 acc[8];
#pragma unroll
            for (int j = 0; j < 8; ++j) acc[j] = 0ull;
            const float* Wg = Wx + (long long)g * IPT * H + k;
#pragma unroll 4
            for (int i = 0; i < IPT; ++i) {
                const u64 wd = dup2(Wg[(long long)i * H]);
#pragma unroll
                for (int j = 0; j < 8; ++j)
                    fma2(acc[j], *(const u64*)&xsT[i][t0 + 2 * j], wd);
            }
#pragma unroll
            for (int j = 0; j < 8; ++j) {
                float v0, v1; un2(acc[j], v0, v1);
#pragma unroll
                for (int half = 0; half < 2; ++half) {
                    const int tt = 2 * j + half;
                    const int t = t0 + tt;
                    const float v = half ? v1 : v0;
                    float* At = Ab + (long long)t * 6 * H;
                    if (g == 0)      At[0]     = v + bgv[0];
                    else if (g == 1) At[H]     = v + bgv[1];
                    else if (g == 2) At[2 * H] = v + bgv[2];
                    else if (g == 3) At[3 * H] = v + Tts[t] * wt4 + Dts[t] * wt5 + bgv[3];
                    else if (g == 4) T1v[tt] = sigf(v + sigf(Tts[t] * wt0) + bgv[4]);
                    else if (g == 5) T2v[tt] = sigf(v + sigf(Tts[t] * wt1) + bgv[5]);
                    else if (g == 6) At[4 * H] = T1v[tt] * sigf(v + sigf(Dts[t] * wt2) + bgv[6]);
                    else             At[5 * H] = T2v[tt] * sigf(v + sigf(Dts[t] * wt3) + bgv[7]);
                }
            }
        }
    }
}

// ---------------- qp = x_q @ Wc + bc ----------------
__global__ void __launch_bounds__(128) qp_kernel(const float* __restrict__ x_q)
{
    const int bt = blockIdx.x, k = threadIdx.x;
    __shared__ float xqT[Q][12];
    const float* xp = x_q + (long long)bt * S * Q;
    for (int idx = k; idx < S * Q; idx += 128) {
        const int s = idx >> 7, q = idx & 127;
        xqT[q][s] = xp[idx];
    }
    __syncthreads();
    const float bcv = g_bc[k];
    u64 acc[5];
#pragma unroll
    for (int p = 0; p < 5; ++p) acc[p] = dup2(bcv);
#pragma unroll 4
    for (int i = 0; i < Q; ++i) {
        const u64 wd = dup2(g_Wc[i * H + k]);
#pragma unroll
        for (int p = 0; p < 5; ++p)
            fma2(acc[p], *(const u64*)&xqT[i][2 * p], wd);
    }
    float* o = g_qp + (long long)bt * S * H + k;
#pragma unroll
    for (int p = 0; p < 5; ++p) {
        float v0, v1; un2(acc[p], v0, v1);
        o[(2 * p) * H] = v0; o[(2 * p + 1) * H] = v1;
    }
}

// ---------------- perm (kl descending, stable) + nvinv ----------------
__global__ void __launch_bounds__(256) perm_kernel(const int* __restrict__ keys_length)
{
    __shared__ int kls[B];
    const int b = threadIdx.x;
    kls[b] = keys_length[b];
    __syncthreads();
    const int kb = kls[b];
    int rank = 0;
    for (int j = 0; j < B; ++j) {
        const int kj = kls[j];
        rank += (kj > kb) || (kj == kb && j < b);
    }
    g_perm[rank] = b;
    if (b < T) {
        int cnt = 0;
        for (int j = 0; j < B; ++j) cnt += (b < kls[j]) ? 1 : 0;
        g_nvinv[b] = cnt ? 1.f / (float)cnt : 0.f;
    }
}

// ---------------- recurrent kernel: 256 threads, role-split ----------------
__global__ void __launch_bounds__(256, 1) rec_kernel(
    const float* __restrict__ Wh, const float* __restrict__ Wattn,
    const float* __restrict__ battn, const float* __restrict__ austgn_y,
    const int* __restrict__ keys_length, float* __restrict__ out)
{
    extern __shared__ float sm[];
    const int tid = threadIdx.x;
    const int k = tid & 127, half = tid >> 7;
    const int lane = tid & 31, warp = tid >> 5;
    const int b = g_perm[blockIdx.x];
    const int kl = keys_length[b];

    // preload W1,W2,W3 into smem (48K floats contiguous in Wattn after Wattn0)
    {
        const float4* src = (const float4*)(Wattn + HH);
        float4* dst = (float4*)(sm + SM_W1);
        for (int i = tid; i < 3 * HH / 4; i += 256) dst[i] = src[i];
    }
    // zero hT, bufT
    for (int i = tid; i < 2 * H * 12; i += 256) sm[SM_HT + i] = 0.f;
    __syncthreads();

    float* hT   = sm + SM_HT;
    float* bufT = sm + SM_BUF;

    const float b1v = battn[1 * H + k];
    const float b2v = battn[2 * H + k];
    const float b3v = battn[3 * H + k];

    float c[S];
#pragma unroll
    for (int s = 0; s < S; ++s) c[s] = 0.f;
    float lossacc = 0.f;

    int t = 0;
    for (; t < kl; ++t) {
        // ---- phase A: prefetch cell inputs (half0) + load qp ----
        float a0 = 0.f, a1 = 0.f, a2 = 0.f, a3 = 0.f, td1 = 0.f, td2 = 0.f, yv = 0.f, nvv = 0.f;
        if (half == 0) {
            const float* Ab = g_A + ((long long)((b * T + t) * 6)) * H + k;
            a0 = Ab[0]; a1 = Ab[H]; a2 = Ab[2 * H]; a3 = Ab[3 * H];
            td1 = Ab[4 * H]; td2 = Ab[5 * H];
            yv = austgn_y[b * T + t]; nvv = g_nvinv[t];
        }
        if (t > 0) {
            const float* qpp = g_qp + ((long long)(b * T + t) * S) * H;
#pragma unroll
            for (int j = 0; j < 5; ++j) {
                const int s = half * 5 + j;
                sm[SM_QPS + s * H + k] = qpp[s * H + k];
            }
        }
        __syncthreads();

        if (t > 0) {
            // ---- phase B: scores, octet (8 lanes) per dot ----
            const int nd = S * t;
            const int group = tid >> 3, gl = tid & 7;
            const int iters = (nd + 31) >> 5;
            for (int i = 0; i < iters; ++i) {
                const int idx = group + 32 * i;
                const bool valid = idx < nd;
                int s = 0, tp = 0;
                float acc = 0.f;
                if (valid) {
                    s = idx / t; tp = idx - s * t;
                    const float4* pkr = (const float4*)(g_pk + ((long long)((b * T + tp) * S + s)) * H) + gl * 4;
                    const float4* qr  = (const float4*)(sm + SM_QPS + s * H) + gl * 4;
#pragma unroll
                    for (int j = 0; j < 4; ++j) {
                        const float4 q = qr[j], p = pkr[j];
                        acc += q.x * p.x + q.y * p.y + q.z * p.z + q.w * p.w;
                    }
                }
                acc += __shfl_xor_sync(0xffffffffu, acc, 1);
                acc += __shfl_xor_sync(0xffffffffu, acc, 2);
                acc += __shfl_xor_sync(0xffffffffu, acc, 4);
                if (valid && gl == 0) sm[SM_SSM + s * T + tp] = acc;
            }
            __syncthreads();

            // ---- phase C: softmax per s over 8 warps ----
            for (int s = warp; s < S; s += 8) {
                float* row = sm + SM_SSM + s * T;
                float mx = -1e30f;
                for (int tp = lane; tp < t; tp += 32) mx = fmaxf(mx, row[tp]);
#pragma unroll
                for (int o = 16; o > 0; o >>= 1) mx = fmaxf(mx, __shfl_xor_sync(0xffffffffu, mx, o));
                float sum = 0.f;
                for (int tp = lane; tp < t; tp += 32) {
                    const float e = __expf(row[tp] - mx);
                    row[tp] = e; sum += e;
                }
#pragma unroll
                for (int o = 16; o > 0; o >>= 1) sum += __shfl_xor_sync(0xffffffffu, sum, o);
                const float inv = __fdividef(1.f, sum);
                for (int tp = lane; tp < t; tp += 32) row[tp] *= inv;
            }
            __syncthreads();

            // ---- phase D: ctx, s-split 4/6 ----
            if (half == 0) {
                float cx[4] = {0.f, 0.f, 0.f, 0.f};
                const float* pvb = g_pv + ((long long)b * T * S) * H + k;
                for (int tp = 0; tp < t; ++tp) {
                    const float* pvr = pvb + (long long)tp * S * H;
#pragma unroll
                    for (int s = 0; s < 4; ++s) cx[s] += sm[SM_SSM + s * T + tp] * pvr[s * H];
                }
#pragma unroll
                for (int s = 0; s < 4; ++s) bufT[k * 12 + s] = cx[s];
            } else {
                float cx[6] = {0.f, 0.f, 0.f, 0.f, 0.f, 0.f};
                const float* pvb = g_pv + ((long long)b * T * S) * H + k + 4 * H;
                for (int tp = 0; tp < t; ++tp) {
                    const float* pvr = pvb + (long long)tp * S * H;
#pragma unroll
                    for (int s = 0; s < 6; ++s) cx[s] += sm[SM_SSM + (s + 4) * T + tp] * pvr[s * H];
                }
#pragma unroll
                for (int s = 0; s < 6; ++s) bufT[k * 12 + 4 + s] = cx[s];
            }
            __syncthreads();
        }

        // ---- phase E: combined gate + at GEMMs ----
        u64 A0[5], A1[5], At2[2];     // half0
        if (half == 0) {
#pragma unroll
            for (int p = 0; p < 5; ++p) { A0[p] = 0ull; A1[p] = 0ull; }
            At2[0] = dup2(b3v); At2[1] = dup2(b3v);
            const float* Wh0 = Wh + k;
            const float* Wh1 = Wh + HH + k;
#pragma unroll 4
            for (int h = 0; h < H; ++h) {
                const u64 w0 = dup2(Wh0[h * H]);
                const u64 w1 = dup2(Wh1[h * H]);
                const u64 w3 = dup2(sm[SM_W3 + h * H + k]);
                const float* hr = hT + h * 12;
                const float* br = bufT + h * 12;
#pragma unroll
                for (int p = 0; p < 5; ++p) {
                    const u64 hp = *(const u64*)(hr + 2 * p);
                    fma2(A0[p], hp, w0); fma2(A1[p], hp, w1);
                }
                fma2(At2[0], *(const u64*)(br),     w3);
                fma2(At2[1], *(const u64*)(br + 2), w3);
            }
        } else {
            u64 A2[5], A3[5], At3[3];
#pragma unroll
            for (int p = 0; p < 5; ++p) { A2[p] = 0ull; A3[p] = 0ull; }
#pragma unroll
            for (int j = 0; j < 3; ++j) At3[j] = dup2(b3v);
            const float* Wh2 = Wh + 2 * HH + k;
            const float* Wh3 = Wh + 3 * HH + k;
#pragma unroll 4
            for (int h = 0; h < H; ++h) {
                const u64 w2  = dup2(Wh2[h * H]);
                const u64 w3g = dup2(Wh3[h * H]);
                const u64 w3a = dup2(sm[SM_W3 + h * H + k]);
                const float* hr = hT + h * 12;
                const float* br = bufT + h * 12;
#pragma unroll
                for (int p = 0; p < 5; ++p) {
                    const u64 hp = *(const u64*)(hr + 2 * p);
                    fma2(A2[p], hp, w2); fma2(A3[p], hp, w3g);
                }
#pragma unroll
                for (int j = 0; j < 3; ++j)
                    fma2(At3[j], *(const u64*)(br + 4 + 2 * j), w3a);
            }
            // stage g2, g3, at[4..9]
#pragma unroll
            for (int p = 0; p < 5; ++p) {
                float v0, v1;
                un2(A2[p], v0, v1);
                sm[SM_ST2 + (2 * p) * H + k] = v0; sm[SM_ST2 + (2 * p + 1) * H + k] = v1;
                un2(A3[p], v0, v1);
                sm[SM_ST3 + (2 * p) * H + k] = v0; sm[SM_ST3 + (2 * p + 1) * H + k] = v1;
            }
#pragma unroll
            for (int j = 0; j < 3; ++j) {
                float v0, v1; un2(At3[j], v0, v1);
                sm[SM_ATS + (2 * j) * H + k] = v0; sm[SM_ATS + (2 * j + 1) * H + k] = v1;
            }
        }
        __syncthreads();

        // ---- phase F: cell (half0 only) ----
        if (half == 0) {
            float G0[S], G1[S], at0[4];
#pragma unroll
            for (int p = 0; p < 5; ++p) {
                un2(A0[p], G0[2 * p], G0[2 * p + 1]);
                un2(A1[p], G1[2 * p], G1[2 * p + 1]);
            }
            un2(At2[0], at0[0], at0[1]);
            un2(At2[1], at0[2], at0[3]);
            float bsum = 0.f;
#pragma unroll
            for (int s = 0; s < S; ++s) {
                const float g2 = sm[SM_ST2 + s * H + k];
                const float g3 = sm[SM_ST3 + s * H + k];
                float atv = 1.f;
                if (t > 0) atv = (s < 4) ? at0[s] : sm[SM_ATS + (s - 4) * H + k];
                const float it = sigf(a0 + G0[s]);
                const float ft = sigf(a1 + G1[s]);
                const float ct = tanhfast(a2 + g2);
                const float ot = sigf(a3 + g3);
                const float itp = it * atv, ftp = ft * atv;
                const float fc = ftp * c[s];
                const float ic = itp * ct;
                const float chat = fc + ic * td1;
                c[s] = fc + ic * td2;
                const float hn = ot * tanhfast(chat);
                hT[k * 12 + s] = hn;
                const float p = fminf(fmaxf(hn, 1e-7f), 1.f - 1e-7f);
                bsum += -(yv * __logf(p) + (1.f - yv) * __logf(1.f - p));
            }
            lossacc += bsum * nvv;
        }
        __syncthreads();

        // ---- phase G: pk / pv GEMMs + output ----
        if (half == 0) {
            u64 P[5];
#pragma unroll
            for (int p = 0; p < 5; ++p) P[p] = dup2(b1v);
#pragma unroll 4
            for (int h = 0; h < H; ++h) {
                const u64 w = dup2(sm[SM_W1 + h * H + k]);
                const float* hr = hT + h * 12;
#pragma unroll
                for (int p = 0; p < 5; ++p)
                    fma2(P[p], *(const u64*)(hr + 2 * p), w);
            }
            float* pkp = g_pk + ((long long)((b * T + t) * S)) * H + k;
#pragma unroll
            for (int p = 0; p < 5; ++p) {
                float v0, v1; un2(P[p], v0, v1);
                pkp[(2 * p) * H] = v0; pkp[(2 * p + 1) * H] = v1;
            }
        } else {
            u64 P[5];
#pragma unroll
            for (int p = 0; p < 5; ++p) P[p] = dup2(b2v);
#pragma unroll 4
            for (int h = 0; h < H; ++h) {
                const u64 w = dup2(sm[SM_W2 + h * H + k]);
                const float* hr = hT + h * 12;
#pragma unroll
                for (int p = 0; p < 5; ++p)
                    fma2(P[p], *(const u64*)(hr + 2 * p), w);
            }
            float* pvp = g_pv + ((long long)((b * T + t) * S)) * H + k;
#pragma unroll
            for (int p = 0; p < 5; ++p) {
                float v0, v1; un2(P[p], v0, v1);
                pvp[(2 * p) * H] = v0; pvp[(2 * p + 1) * H] = v1;
            }
            // hidden_seq_attn output
            float* outp = out + ((long long)((b * T + t) * S)) * H + k;
#pragma unroll
            for (int s = 0; s < S; ++s) outp[s * H] = hT[k * 12 + s];
        }
        __syncthreads();
    }

    // masked steps: zeros (split s-range across halves)
    for (; t < T; ++t) {
        float* outp = out + ((long long)((b * T + t) * S)) * H + k;
#pragma unroll
        for (int j = 0; j < 5; ++j) outp[(half * 5 + j) * H] = 0.f;
    }

    // final h, c (half0)
    if (half == 0) {
        float* oh = out + HSEQ_ELEMS + ((long long)b * S) * H + k;
#pragma unroll
        for (int s = 0; s < S; ++s) oh[s * H] = hT[k * 12 + s];
        float* oc = oh + HC_ELEMS;
#pragma unroll
        for (int s = 0; s < S; ++s) oc[s * H] = c[s];
    }

    // loss partial (half1 contributes zeros)
    float v = (half == 0) ? lossacc : 0.f;
#pragma unroll
    for (int o = 16; o > 0; o >>= 1) v += __shfl_xor_sync(0xffffffffu, v, o);
    if (lane == 0) sm[SM_RED + warp] = v;
    __syncthreads();
    if (tid == 0) {
        float sum = 0.f;
#pragma unroll
        for (int w = 0; w < 8; ++w) sum += sm[SM_RED + w];
        g_losspart[b] = sum * (1.f / (float)(S * H));
    }
}

// ---------------- final loss reduction ----------------
__global__ void loss_kernel(float* __restrict__ out)
{
    __shared__ float smr[B];
    smr[threadIdx.x] = g_losspart[threadIdx.x];
    __syncthreads();
    for (int off = B / 2; off > 0; off >>= 1) {
        if (threadIdx.x < off) smr[threadIdx.x] += smr[threadIdx.x + off];
        __syncthreads();
    }
    if (threadIdx.x == 0) out[HSEQ_ELEMS + 2 * HC_ELEMS] = smr[0];
}

// ---------------- launch ----------------
extern "C" void kernel_launch(void* const* d_in, const int* in_sizes, int n_in,
                              void* d_out, int out_size)
{
    (void)in_sizes; (void)n_in; (void)out_size;
    const float* inputs      = (const float*)d_in[0];
    const float* x_q         = (const float*)d_in[1];
    const float* austgn_y    = (const float*)d_in[2];
    const int*   keys_length = (const int*)  d_in[3];
    const float* Wx          = (const float*)d_in[4];
    const float* Wh          = (const float*)d_in[5];
    const float* Wts         = (const float*)d_in[6];
    const float* bg          = (const float*)d_in[7];
    const float* Wa          = (const float*)d_in[8];
    const float* ba          = (const float*)d_in[9];
    const float* Wattn       = (const float*)d_in[10];
    const float* battn       = (const float*)d_in[11];
    float* out = (float*)d_out;

    static int smem_set = 0;
    if (!smem_set) {
        cudaFuncSetAttribute(rec_kernel, cudaFuncAttributeMaxDynamicSharedMemorySize,
                             SM_TOTAL * (int)sizeof(float));
        smem_set = 1;
    }

    fold_kernel<<<H, H>>>(Wa, ba, Wattn, battn);
    pre_kernel<<<B, 128>>>(inputs, Wx, Wts, bg);
    qp_kernel<<<B * T, 128>>>(x_q);
    perm_kernel<<<1, B>>>(keys_length);
    rec_kernel<<<B, 256, SM_TOTAL * (int)sizeof(float)>>>(
        Wh, Wattn, battn, austgn_y, keys_length, out);
    loss_kernel<<<1, B>>>(out);
}

// round 6
// speedup vs baseline: 2.9686x; 1.0947x over previous
#include <cuda_runtime.h>
#include <math.h>

namespace {
constexpr int B = 256, T = 64, S = 10, H = 128, IPT = 128, Q = 128;
constexpr int ROWLEN = 2 + IPT;
constexpr int HH = H * H;
constexpr long long HSEQ_ELEMS = (long long)B * T * S * H;
constexpr long long HC_ELEMS   = (long long)B * S * H;
// dynamic smem layout (float offsets)
constexpr int SM_W1  = 0;
constexpr int SM_W2  = SM_W1 + HH;
constexpr int SM_W3  = SM_W2 + HH;
constexpr int SM_HT  = SM_W3 + HH;          // [128][12]
constexpr int SM_BUF = SM_HT + H * 12;      // [128][12]
constexpr int SM_QPS = SM_BUF + H * 12;     // [10][128]
constexpr int SM_SSM = SM_QPS + S * H;      // [10][64]
constexpr int SM_ST2 = SM_SSM + S * T;      // [10][128]
constexpr int SM_ST3 = SM_ST2 + S * H;      // [10][128]
constexpr int SM_ATS = SM_ST3 + S * H;      // [6][128]
constexpr int SM_RED = SM_ATS + 6 * H;      // [8]
constexpr int SM_TOTAL = SM_RED + 8;        // 57480 floats = 229920 B
}

// ---------------- scratch ----------------
__device__ float g_qp[B * T * S * H];
__device__ float g_A [B * T * 6 * H];
__device__ float g_pk[B * T * S * H];
__device__ float g_pv[B * T * S * H];
__device__ float g_Wc[H * H];
__device__ float g_bc[H];
__device__ float2 g_Wh01[H * H];        // interleaved gates 0,1
__device__ float2 g_Wh23[H * H];        // interleaved gates 2,3
__device__ float g_nvinv[T];
__device__ float g_losspart[B];
__device__ int   g_perm[B];

// ---------------- f32x2 helpers ----------------
using u64 = unsigned long long;
__device__ __forceinline__ u64 pk2(float lo, float hi) {
    u64 r; asm("mov.b64 %0,{%1,%2};" : "=l"(r) : "f"(lo), "f"(hi)); return r;
}
__device__ __forceinline__ u64 dup2(float x) { return pk2(x, x); }
__device__ __forceinline__ void un2(u64 v, float& a, float& b) {
    asm("mov.b64 {%0,%1},%2;" : "=f"(a), "=f"(b) : "l"(v));
}
__device__ __forceinline__ void fma2(u64& d, u64 a, u64 b) {
    asm("fma.rn.f32x2 %0,%1,%2,%0;" : "+l"(d) : "l"(a), "l"(b));
}

__device__ __forceinline__ float sigf(float x) {
    return __fdividef(1.f, 1.f + __expf(-x));
}
__device__ __forceinline__ float tanhfast(float x) {
    return __fdividef(2.f, 1.f + __expf(-2.f * x)) - 1.f;
}

// ---------------- fold: q-weights + Wh interleave + perm/nvinv ----------------
// blocks 0..127   : g_Wc / g_bc (fold q projection, scale folded)
// blocks 128..255 : Wh gate-pair interleave; block 128 also perm + nvinv
__global__ void __launch_bounds__(128) fold_kernel(
    const float* __restrict__ Wa, const float* __restrict__ ba,
    const float* __restrict__ Wattn, const float* __restrict__ battn,
    const float* __restrict__ Wh, const int* __restrict__ keys_length)
{
    const int bx = blockIdx.x, tid = threadIdx.x;
    if (bx < 128) {
        const int q = bx, h = tid;
        const float scale = 0.08838834764831845f;
        float acc = 0.f;
        for (int j = 0; j < H; ++j) acc += Wa[q * H + j] * Wattn[j * H + h];
        g_Wc[q * H + h] = acc * scale;
        if (q == 0) {
            float bacc = battn[h];
            for (int j = 0; j < H; ++j) bacc += ba[j] * Wattn[j * H + h];
            g_bc[h] = bacc * scale;
        }
        return;
    }
    // interleave: one element per thread
    const int e = (bx - 128) * 128 + tid;           // 0..16383
    g_Wh01[e] = make_float2(Wh[e], Wh[HH + e]);
    g_Wh23[e] = make_float2(Wh[2 * HH + e], Wh[3 * HH + e]);

    if (bx == 128) {
        // perm (kl descending, stable) — each thread handles b = tid, tid+128
#pragma unroll
        for (int half = 0; half < 2; ++half) {
            const int b = tid + half * 128;
            const int kb = keys_length[b];
            int rank = 0;
            for (int j = 0; j < B; ++j) {
                const int kj = keys_length[j];
                rank += (kj > kb) || (kj == kb && j < b);
            }
            g_perm[rank] = b;
        }
        if (tid < T) {
            int cnt = 0;
            for (int j = 0; j < B; ++j) cnt += (tid < keys_length[j]) ? 1 : 0;
            g_nvinv[tid] = cnt ? 1.f / (float)cnt : 0.f;
        }
    }
}

// ---------------- precompute A[B,T,6,H] (only t < kl) ----------------
__global__ void __launch_bounds__(128) pre_kernel(
    const float* __restrict__ inputs, const float* __restrict__ Wx,
    const float* __restrict__ Wts, const float* __restrict__ bg,
    const int* __restrict__ keys_length)
{
    const int b = blockIdx.x, k = threadIdx.x;
    const int kl = keys_length[b];
    if (kl == 0) return;
    __shared__ float xsT[IPT][66];
    __shared__ float Tts[T], Dts[T];
    const int tmax = kl;   // only need t < kl
    for (int idx = k; idx < tmax * IPT; idx += 128) {
        const int t = idx >> 7, i = idx & 127;
        xsT[i][t] = inputs[(long long)(b * T + t) * ROWLEN + 2 + i];
    }
    if (k < tmax) {
        Tts[k] = inputs[(long long)(b * T + k) * ROWLEN + 0];
        Dts[k] = inputs[(long long)(b * T + k) * ROWLEN + 1];
    }
    __syncthreads();

    const float wt0 = Wts[0 * H + k], wt1 = Wts[1 * H + k];
    const float wt2 = Wts[2 * H + k], wt3 = Wts[3 * H + k];
    const float wt4 = Wts[4 * H + k], wt5 = Wts[5 * H + k];
    float bgv[8];
#pragma unroll
    for (int g = 0; g < 8; ++g) bgv[g] = bg[g * H + k];

    float* Ab = g_A + ((long long)b * T * 6) * H + k;

    for (int t0 = 0; t0 < tmax; t0 += 16) {
        const int nt = min(16, tmax - t0);
        float T1v[16], T2v[16];
#pragma unroll
        for (int g = 0; g < 8; ++g) {
            u64 acc[8];
#pragma unroll
            for (int j = 0; j < 8; ++j) acc[j] = 0ull;
            const float* Wg = Wx + (long long)g * IPT * H + k;
#pragma unroll 4
            for (int i = 0; i < IPT; ++i) {
                const u64 wd = dup2(Wg[(long long)i * H]);
#pragma unroll
                for (int j = 0; j < 8; ++j)
                    fma2(acc[j], *(const u64*)&xsT[i][t0 + 2 * j], wd);
            }
#pragma unroll
            for (int j = 0; j < 8; ++j) {
                float v0, v1; un2(acc[j], v0, v1);
#pragma unroll
                for (int half = 0; half < 2; ++half) {
                    const int tt = 2 * j + half;
                    if (tt >= nt) continue;
                    const int t = t0 + tt;
                    const float v = half ? v1 : v0;
                    float* At = Ab + (long long)t * 6 * H;
                    if (g == 0)      At[0]     = v + bgv[0];
                    else if (g == 1) At[H]     = v + bgv[1];
                    else if (g == 2) At[2 * H] = v + bgv[2];
                    else if (g == 3) At[3 * H] = v + Tts[t] * wt4 + Dts[t] * wt5 + bgv[3];
                    else if (g == 4) T1v[tt] = sigf(v + sigf(Tts[t] * wt0) + bgv[4]);
                    else if (g == 5) T2v[tt] = sigf(v + sigf(Tts[t] * wt1) + bgv[5]);
                    else if (g == 6) At[4 * H] = T1v[tt] * sigf(v + sigf(Dts[t] * wt2) + bgv[6]);
                    else             At[5 * H] = T2v[tt] * sigf(v + sigf(Dts[t] * wt3) + bgv[7]);
                }
            }
        }
    }
}

// ---------------- qp = x_q @ Wc + bc (only 1 <= t < kl) ----------------
__global__ void __launch_bounds__(128) qp_kernel(
    const float* __restrict__ x_q, const int* __restrict__ keys_length)
{
    const int bt = blockIdx.x, k = threadIdx.x;
    const int b = bt >> 6, t = bt & 63;
    if (t == 0 || t >= keys_length[b]) return;   // never read
    __shared__ float xqT[Q][12];
    const float* xp = x_q + (long long)bt * S * Q;
    for (int idx = k; idx < S * Q; idx += 128) {
        const int s = idx >> 7, q = idx & 127;
        xqT[q][s] = xp[idx];
    }
    __syncthreads();
    const float bcv = g_bc[k];
    u64 acc[5];
#pragma unroll
    for (int p = 0; p < 5; ++p) acc[p] = dup2(bcv);
#pragma unroll 4
    for (int i = 0; i < Q; ++i) {
        const u64 wd = dup2(g_Wc[i * H + k]);
#pragma unroll
        for (int p = 0; p < 5; ++p)
            fma2(acc[p], *(const u64*)&xqT[i][2 * p], wd);
    }
    float* o = g_qp + (long long)bt * S * H + k;
#pragma unroll
    for (int p = 0; p < 5; ++p) {
        float v0, v1; un2(acc[p], v0, v1);
        o[(2 * p) * H] = v0; o[(2 * p + 1) * H] = v1;
    }
}

// ---------------- recurrent kernel: 256 threads, role-split ----------------
__global__ void __launch_bounds__(256, 1) rec_kernel(
    const float* __restrict__ Wattn, const float* __restrict__ battn,
    const float* __restrict__ austgn_y, const int* __restrict__ keys_length,
    float* __restrict__ out)
{
    extern __shared__ float sm[];
    const int tid = threadIdx.x;
    const int k = tid & 127, half = tid >> 7;
    const int lane = tid & 31, warp = tid >> 5;
    const int b = g_perm[blockIdx.x];
    const int kl = keys_length[b];

    // preload W1,W2,W3 into smem (contiguous in Wattn after Wattn0)
    {
        const float4* src = (const float4*)(Wattn + HH);
        float4* dst = (float4*)(sm + SM_W1);
        for (int i = tid; i < 3 * HH / 4; i += 256) dst[i] = src[i];
    }
    for (int i = tid; i < 2 * H * 12; i += 256) sm[SM_HT + i] = 0.f;
    __syncthreads();

    float* hT   = sm + SM_HT;
    float* bufT = sm + SM_BUF;

    const float b1v = battn[1 * H + k];
    const float b2v = battn[2 * H + k];
    const float b3v = battn[3 * H + k];

    float c[S];
#pragma unroll
    for (int s = 0; s < S; ++s) c[s] = 0.f;
    float lossacc = 0.f;

    int t = 0;
    for (; t < kl; ++t) {
        // ---- phase A: prefetch cell inputs (half0) + load qp ----
        float a0 = 0.f, a1 = 0.f, a2 = 0.f, a3 = 0.f, td1 = 0.f, td2 = 0.f, yv = 0.f, nvv = 0.f;
        if (half == 0) {
            const float* Ab = g_A + ((long long)((b * T + t) * 6)) * H + k;
            a0 = Ab[0]; a1 = Ab[H]; a2 = Ab[2 * H]; a3 = Ab[3 * H];
            td1 = Ab[4 * H]; td2 = Ab[5 * H];
            yv = austgn_y[b * T + t]; nvv = g_nvinv[t];
        }
        if (t > 0) {
            const float* qpp = g_qp + ((long long)(b * T + t) * S) * H;
#pragma unroll
            for (int j = 0; j < 5; ++j) {
                const int s = half * 5 + j;
                sm[SM_QPS + s * H + k] = qpp[s * H + k];
            }
        }
        __syncthreads();

        if (t > 0) {
            // ---- phase B: scores, octet (8 lanes) per dot ----
            const int nd = S * t;
            const int group = tid >> 3, gl = tid & 7;
            const int iters = (nd + 31) >> 5;
            for (int i = 0; i < iters; ++i) {
                const int idx = group + 32 * i;
                const bool valid = idx < nd;
                int s = 0, tp = 0;
                float acc = 0.f;
                if (valid) {
                    s = idx / t; tp = idx - s * t;
                    const float4* pkr = (const float4*)(g_pk + ((long long)((b * T + tp) * S + s)) * H) + gl * 4;
                    const float4* qr  = (const float4*)(sm + SM_QPS + s * H) + gl * 4;
#pragma unroll
                    for (int j = 0; j < 4; ++j) {
                        const float4 q = qr[j], p = pkr[j];
                        acc += q.x * p.x + q.y * p.y + q.z * p.z + q.w * p.w;
                    }
                }
                acc += __shfl_xor_sync(0xffffffffu, acc, 1);
                acc += __shfl_xor_sync(0xffffffffu, acc, 2);
                acc += __shfl_xor_sync(0xffffffffu, acc, 4);
                if (valid && gl == 0) sm[SM_SSM + s * T + tp] = acc;
            }
            __syncthreads();

            // ---- phase C: softmax per s over 8 warps ----
            for (int s = warp; s < S; s += 8) {
                float* row = sm + SM_SSM + s * T;
                float mx = -1e30f;
                for (int tp = lane; tp < t; tp += 32) mx = fmaxf(mx, row[tp]);
#pragma unroll
                for (int o = 16; o > 0; o >>= 1) mx = fmaxf(mx, __shfl_xor_sync(0xffffffffu, mx, o));
                float sum = 0.f;
                for (int tp = lane; tp < t; tp += 32) {
                    const float e = __expf(row[tp] - mx);
                    row[tp] = e; sum += e;
                }
#pragma unroll
                for (int o = 16; o > 0; o >>= 1) sum += __shfl_xor_sync(0xffffffffu, sum, o);
                const float inv = __fdividef(1.f, sum);
                for (int tp = lane; tp < t; tp += 32) row[tp] *= inv;
            }
            __syncthreads();

            // ---- phase D: ctx, s-split 4/6 ----
            if (half == 0) {
                float cx[4] = {0.f, 0.f, 0.f, 0.f};
                const float* pvb = g_pv + ((long long)b * T * S) * H + k;
#pragma unroll 4
                for (int tp = 0; tp < t; ++tp) {
                    const float* pvr = pvb + (long long)tp * S * H;
#pragma unroll
                    for (int s = 0; s < 4; ++s) cx[s] += sm[SM_SSM + s * T + tp] * pvr[s * H];
                }
#pragma unroll
                for (int s = 0; s < 4; ++s) bufT[k * 12 + s] = cx[s];
            } else {
                float cx[6] = {0.f, 0.f, 0.f, 0.f, 0.f, 0.f};
                const float* pvb = g_pv + ((long long)b * T * S) * H + k + 4 * H;
#pragma unroll 4
                for (int tp = 0; tp < t; ++tp) {
                    const float* pvr = pvb + (long long)tp * S * H;
#pragma unroll
                    for (int s = 0; s < 6; ++s) cx[s] += sm[SM_SSM + (s + 4) * T + tp] * pvr[s * H];
                }
#pragma unroll
                for (int s = 0; s < 6; ++s) bufT[k * 12 + 4 + s] = cx[s];
            }
            __syncthreads();
        }

        // ---- phase E: combined gate + at GEMMs (interleaved Wh pairs) ----
        u64 A0[5], A1[5], At2[2];     // half0
        if (half == 0) {
#pragma unroll
            for (int p = 0; p < 5; ++p) { A0[p] = 0ull; A1[p] = 0ull; }
            At2[0] = dup2(b3v); At2[1] = dup2(b3v);
            const float2* Wp = g_Wh01 + k;
#pragma unroll 4
            for (int h = 0; h < H; ++h) {
                const float2 w01 = Wp[h * H];
                const u64 w0 = dup2(w01.x);
                const u64 w1 = dup2(w01.y);
                const u64 w3 = dup2(sm[SM_W3 + h * H + k]);
                const float* hr = hT + h * 12;
                const float* br = bufT + h * 12;
#pragma unroll
                for (int p = 0; p < 5; ++p) {
                    const u64 hp = *(const u64*)(hr + 2 * p);
                    fma2(A0[p], hp, w0); fma2(A1[p], hp, w1);
                }
                fma2(At2[0], *(const u64*)(br),     w3);
                fma2(At2[1], *(const u64*)(br + 2), w3);
            }
        } else {
            u64 A2[5], A3[5], At3[3];
#pragma unroll
            for (int p = 0; p < 5; ++p) { A2[p] = 0ull; A3[p] = 0ull; }
#pragma unroll
            for (int j = 0; j < 3; ++j) At3[j] = dup2(b3v);
            const float2* Wp = g_Wh23 + k;
#pragma unroll 4
            for (int h = 0; h < H; ++h) {
                const float2 w23 = Wp[h * H];
                const u64 w2  = dup2(w23.x);
                const u64 w3g = dup2(w23.y);
                const u64 w3a = dup2(sm[SM_W3 + h * H + k]);
                const float* hr = hT + h * 12;
                const float* br = bufT + h * 12;
#pragma unroll
                for (int p = 0; p < 5; ++p) {
                    const u64 hp = *(const u64*)(hr + 2 * p);
                    fma2(A2[p], hp, w2); fma2(A3[p], hp, w3g);
                }
#pragma unroll
                for (int j = 0; j < 3; ++j)
                    fma2(At3[j], *(const u64*)(br + 4 + 2 * j), w3a);
            }
            // stage g2, g3, at[4..9]
#pragma unroll
            for (int p = 0; p < 5; ++p) {
                float v0, v1;
                un2(A2[p], v0, v1);
                sm[SM_ST2 + (2 * p) * H + k] = v0; sm[SM_ST2 + (2 * p + 1) * H + k] = v1;
                un2(A3[p], v0, v1);
                sm[SM_ST3 + (2 * p) * H + k] = v0; sm[SM_ST3 + (2 * p + 1) * H + k] = v1;
            }
#pragma unroll
            for (int j = 0; j < 3; ++j) {
                float v0, v1; un2(At3[j], v0, v1);
                sm[SM_ATS + (2 * j) * H + k] = v0; sm[SM_ATS + (2 * j + 1) * H + k] = v1;
            }
        }
        __syncthreads();

        // ---- phase F: cell (half0 only) ----
        if (half == 0) {
            float G0[S], G1[S], at0[4];
#pragma unroll
            for (int p = 0; p < 5; ++p) {
                un2(A0[p], G0[2 * p], G0[2 * p + 1]);
                un2(A1[p], G1[2 * p], G1[2 * p + 1]);
            }
            un2(At2[0], at0[0], at0[1]);
            un2(At2[1], at0[2], at0[3]);
            float bsum = 0.f;
#pragma unroll
            for (int s = 0; s < S; ++s) {
                const float g2 = sm[SM_ST2 + s * H + k];
                const float g3 = sm[SM_ST3 + s * H + k];
                float atv = 1.f;
                if (t > 0) atv = (s < 4) ? at0[s] : sm[SM_ATS + (s - 4) * H + k];
                const float it = sigf(a0 + G0[s]);
                const float ft = sigf(a1 + G1[s]);
                const float ct = tanhfast(a2 + g2);
                const float ot = sigf(a3 + g3);
                const float itp = it * atv, ftp = ft * atv;
                const float fc = ftp * c[s];
                const float ic = itp * ct;
                const float chat = fc + ic * td1;
                c[s] = fc + ic * td2;
                const float hn = ot * tanhfast(chat);
                hT[k * 12 + s] = hn;
                const float p = fminf(fmaxf(hn, 1e-7f), 1.f - 1e-7f);
                bsum += -(yv * __logf(p) + (1.f - yv) * __logf(1.f - p));
            }
            lossacc += bsum * nvv;
        }
        __syncthreads();

        // ---- phase G: pk / pv GEMMs + output ----
        if (half == 0) {
            u64 P[5];
#pragma unroll
            for (int p = 0; p < 5; ++p) P[p] = dup2(b1v);
#pragma unroll 4
            for (int h = 0; h < H; ++h) {
                const u64 w = dup2(sm[SM_W1 + h * H + k]);
                const float* hr = hT + h * 12;
#pragma unroll
                for (int p = 0; p < 5; ++p)
                    fma2(P[p], *(const u64*)(hr + 2 * p), w);
            }
            float* pkp = g_pk + ((long long)((b * T + t) * S)) * H + k;
#pragma unroll
            for (int p = 0; p < 5; ++p) {
                float v0, v1; un2(P[p], v0, v1);
                pkp[(2 * p) * H] = v0; pkp[(2 * p + 1) * H] = v1;
            }
        } else {
            u64 P[5];
#pragma unroll
            for (int p = 0; p < 5; ++p) P[p] = dup2(b2v);
#pragma unroll 4
            for (int h = 0; h < H; ++h) {
                const u64 w = dup2(sm[SM_W2 + h * H + k]);
                const float* hr = hT + h * 12;
#pragma unroll
                for (int p = 0; p < 5; ++p)
                    fma2(P[p], *(const u64*)(hr + 2 * p), w);
            }
            float* pvp = g_pv + ((long long)((b * T + t) * S)) * H + k;
#pragma unroll
            for (int p = 0; p < 5; ++p) {
                float v0, v1; un2(P[p], v0, v1);
                pvp[(2 * p) * H] = v0; pvp[(2 * p + 1) * H] = v1;
            }
            // hidden_seq_attn output
            float* outp = out + ((long long)((b * T + t) * S)) * H + k;
#pragma unroll
            for (int s = 0; s < S; ++s) outp[s * H] = hT[k * 12 + s];
        }
        __syncthreads();
    }

    // masked steps: zeros (split s-range across halves)
    for (; t < T; ++t) {
        float* outp = out + ((long long)((b * T + t) * S)) * H + k;
#pragma unroll
        for (int j = 0; j < 5; ++j) outp[(half * 5 + j) * H] = 0.f;
    }

    // final h, c (half0)
    if (half == 0) {
        float* oh = out + HSEQ_ELEMS + ((long long)b * S) * H + k;
#pragma unroll
        for (int s = 0; s < S; ++s) oh[s * H] = hT[k * 12 + s];
        float* oc = oh + HC_ELEMS;
#pragma unroll
        for (int s = 0; s < S; ++s) oc[s * H] = c[s];
    }

    // loss partial (half1 contributes zeros)
    float v = (half == 0) ? lossacc : 0.f;
#pragma unroll
    for (int o = 16; o > 0; o >>= 1) v += __shfl_xor_sync(0xffffffffu, v, o);
    if (lane == 0) sm[SM_RED + warp] = v;
    __syncthreads();
    if (tid == 0) {
        float sum = 0.f;
#pragma unroll
        for (int w = 0; w < 8; ++w) sum += sm[SM_RED + w];
        g_losspart[b] = sum * (1.f / (float)(S * H));
    }
}

// ---------------- final loss reduction ----------------
__global__ void loss_kernel(float* __restrict__ out)
{
    __shared__ float smr[B];
    smr[threadIdx.x] = g_losspart[threadIdx.x];
    __syncthreads();
    for (int off = B / 2; off > 0; off >>= 1) {
        if (threadIdx.x < off) smr[threadIdx.x] += smr[threadIdx.x + off];
        __syncthreads();
    }
    if (threadIdx.x == 0) out[HSEQ_ELEMS + 2 * HC_ELEMS] = smr[0];
}

// ---------------- launch ----------------
extern "C" void kernel_launch(void* const* d_in, const int* in_sizes, int n_in,
                              void* d_out, int out_size)
{
    (void)in_sizes; (void)n_in; (void)out_size;
    const float* inputs      = (const float*)d_in[0];
    const float* x_q         = (const float*)d_in[1];
    const float* austgn_y    = (const float*)d_in[2];
    const int*   keys_length = (const int*)  d_in[3];
    const float* Wx          = (const float*)d_in[4];
    const float* Wh          = (const float*)d_in[5];
    const float* Wts         = (const float*)d_in[6];
    const float* bg          = (const float*)d_in[7];
    const float* Wa          = (const float*)d_in[8];
    const float* ba          = (const float*)d_in[9];
    const float* Wattn       = (const float*)d_in[10];
    const float* battn       = (const float*)d_in[11];
    float* out = (float*)d_out;

    static int smem_set = 0;
    if (!smem_set) {
        cudaFuncSetAttribute(rec_kernel, cudaFuncAttributeMaxDynamicSharedMemorySize,
                             SM_TOTAL * (int)sizeof(float));
        smem_set = 1;
    }

    fold_kernel<<<256, 128>>>(Wa, ba, Wattn, battn, Wh, keys_length);
    pre_kernel<<<B, 128>>>(inputs, Wx, Wts, bg, keys_length);
    qp_kernel<<<B * T, 128>>>(x_q, keys_length);
    rec_kernel<<<B, 256, SM_TOTAL * (int)sizeof(float)>>>(
        Wattn, battn, austgn_y, keys_length, out);
    loss_kernel<<<1, B>>>(out);
}